// round 4
// baseline (speedup 1.0000x reference)
#include <cuda_runtime.h>

// LSTMTagger: L=262144 sequential steps, H=128 (4H=512 gate rows), I=2.
// Only final h, c, and sigmoid(h.W_out+b) are needed.
// Strategy: single persistent CTA, 512 threads = 1 thread per gate row.
//   - W_hh[r, 0:80]  in registers (80 regs/thread, 512 thr => 40K regs)
//   - W_hh[r, 80:128] in smem, layout [k][row] (conflict-free scalar LDS)
//   - h in smem (float4 broadcast reads), c in registers of threads 0..127
//   - input x streamed through smem in 1024-step chunks
// Full fp32 everywhere (262k-step recurrence; low-precision weights are too
// risky vs rel_err < 1e-3).

#define L_SEQ    262144
#define H_DIM    128
#define G_DIM    512
#define KR       80            // k-columns held in registers
#define KS       (H_DIM - KR)  // 48 k-columns in shared memory
#define CHUNK    1024
#define NTHREADS 512

// smem layout (floats):
//   Wsm  [KS * G_DIM]   = 98304 B
//   h_sh [H_DIM]        =   512 B
//   gact [G_DIM]        =  2048 B
//   xbuf [CHUNK * 2]    =  8192 B
#define SMEM_FLOATS (KS * G_DIM + H_DIM + G_DIM + CHUNK * 2)

__device__ __forceinline__ float sigmoid_f(float x) {
    // 1 / (1 + e^-x); __expf/__fdividef saturate correctly at +-inf
    return __fdividef(1.0f, 1.0f + __expf(-x));
}
__device__ __forceinline__ float tanh_f(float x) {
    // tanh(x) = 1 - 2/(exp(2x)+1); exact limits at +-1 under __expf overflow
    return 1.0f - __fdividef(2.0f, 1.0f + __expf(2.0f * x));
}

__global__ void __launch_bounds__(NTHREADS, 1)
lstm_persistent_kernel(const float* __restrict__ sentence,
                       const float* __restrict__ W_ih,
                       const float* __restrict__ W_hh,
                       const float* __restrict__ b_ih,
                       const float* __restrict__ b_hh,
                       const float* __restrict__ W_out,
                       const float* __restrict__ b_out,
                       float* __restrict__ out)
{
    extern __shared__ float smem[];
    float* Wsm  = smem;                      // [k][row], k in [0,KS)
    float* h_sh = Wsm + KS * G_DIM;          // 128
    float* gact = h_sh + H_DIM;              // 512
    float* xbuf = gact + G_DIM;              // CHUNK*2

    const int r = threadIdx.x;               // gate row 0..511
    const int gate = r >> 7;                 // 0=i 1=f 2=g(tanh) 3=o

    // Per-row constants: xg[t][r] = wih0*x0 + wih1*x1 + (b_ih[r]+b_hh[r])
    const float wih0 = W_ih[2 * r + 0];
    const float wih1 = W_ih[2 * r + 1];
    const float br   = b_ih[r] + b_hh[r];

    // Register-resident slice of W_hh row r
    float Wr[KR];
#pragma unroll
    for (int j = 0; j < KR; ++j) Wr[j] = W_hh[r * H_DIM + j];

    // Shared slice, transposed so lane-consecutive rows are conflict-free
#pragma unroll
    for (int k = 0; k < KS; ++k) Wsm[k * G_DIM + r] = W_hh[r * H_DIM + KR + k];

    float c_reg = 0.0f;                      // valid for r < 128
    if (r < H_DIM) h_sh[r] = 0.0f;
    __syncthreads();

    for (int t0 = 0; t0 < L_SEQ; t0 += CHUNK) {
        // Refill x chunk: 2048 floats = 512 float4, one per thread.
        {
            const float4* src = (const float4*)(sentence + 2 * t0);
            ((float4*)xbuf)[r] = src[r];
        }
        __syncthreads();

#pragma unroll 1
        for (int ti = 0; ti < CHUNK; ++ti) {
            const float x0 = xbuf[2 * ti + 0];
            const float x1 = xbuf[2 * ti + 1];
            float acc0 = fmaf(wih0, x0, br);
            float acc1 = wih1 * x1;

            const float4* h4 = (const float4*)h_sh;
            // k in [0, KR): weights from registers
#pragma unroll
            for (int q = 0; q < KR / 4; ++q) {
                const float4 hv = h4[q];
                acc0 = fmaf(Wr[4 * q + 0], hv.x, acc0);
                acc1 = fmaf(Wr[4 * q + 1], hv.y, acc1);
                acc0 = fmaf(Wr[4 * q + 2], hv.z, acc0);
                acc1 = fmaf(Wr[4 * q + 3], hv.w, acc1);
            }
            // k in [KR, 128): weights from shared, [k][row] layout
#pragma unroll
            for (int q = KR / 4; q < H_DIM / 4; ++q) {
                const float4 hv = h4[q];
                const int kk = 4 * q - KR;
                acc0 = fmaf(Wsm[(kk + 0) * G_DIM + r], hv.x, acc0);
                acc1 = fmaf(Wsm[(kk + 1) * G_DIM + r], hv.y, acc1);
                acc0 = fmaf(Wsm[(kk + 2) * G_DIM + r], hv.z, acc0);
                acc1 = fmaf(Wsm[(kk + 3) * G_DIM + r], hv.w, acc1);
            }
            const float g = acc0 + acc1;

            // Activation: warp-uniform branch (gate constant per warp group)
            const float a = (gate == 2) ? tanh_f(g) : sigmoid_f(g);
            gact[r] = a;
            __syncthreads();

            if (r < H_DIM) {
                const float iv = gact[r];
                const float fv = gact[H_DIM + r];
                const float gv = gact[2 * H_DIM + r];
                const float ov = gact[3 * H_DIM + r];
                c_reg = fmaf(fv, c_reg, iv * gv);
                h_sh[r] = ov * tanh_f(c_reg);
            }
            __syncthreads();
        }
    }

    // Outputs: [0] = sigmoid(h . W_out + b_out), [1..128] = h_n, [129..256] = c_n
    if (r < H_DIM) {
        out[1 + r]         = h_sh[r];
        out[1 + H_DIM + r] = c_reg;
    }
    if (r < 32) {
        float s = 0.0f;
#pragma unroll
        for (int m = 0; m < 4; ++m)
            s = fmaf(h_sh[4 * r + m], W_out[4 * r + m], s);
#pragma unroll
        for (int off = 16; off > 0; off >>= 1)
            s += __shfl_xor_sync(0xffffffffu, s, off);
        if (r == 0) out[0] = sigmoid_f(s + b_out[0]);
    }
}

extern "C" void kernel_launch(void* const* d_in, const int* in_sizes, int n_in,
                              void* d_out, int out_size)
{
    const float* sentence = (const float*)d_in[0];
    const float* W_ih     = (const float*)d_in[1];
    const float* W_hh     = (const float*)d_in[2];
    const float* b_ih     = (const float*)d_in[3];
    const float* b_hh     = (const float*)d_in[4];
    const float* W_out    = (const float*)d_in[5];
    const float* b_out    = (const float*)d_in[6];
    float* out            = (float*)d_out;

    const size_t smem_bytes = (size_t)SMEM_FLOATS * sizeof(float); // ~109 KB
    cudaFuncSetAttribute(lstm_persistent_kernel,
                         cudaFuncAttributeMaxDynamicSharedMemorySize,
                         (int)smem_bytes);

    lstm_persistent_kernel<<<1, NTHREADS, smem_bytes>>>(
        sentence, W_ih, W_hh, b_ih, b_hh, W_out, b_out, out);
}

// round 5
// speedup vs baseline: 1.1513x; 1.1513x over previous
#include <cuda_runtime.h>

// LSTMTagger: 262144 strictly-sequential LSTM steps, H=128 (512 gate rows), I=2.
// Single persistent CTA, 512 threads = 1 thread per gate row.
// R4: packed fma.rn.f32x2 gemv (2 MACs/issue), 96 weight cols in registers
//     (48 x u64 pairs), 32 cols in smem as ulonglong2 quads.
// Full fp32 numerics (f32x2 is IEEE FMA per 32-bit lane).

#define L_SEQ    262144
#define H_DIM    128
#define G_DIM    512
#define KRP      48            // packed weight pairs in registers (96 columns)
#define KSQ      8             // smem weight quads (8*4 = 32 columns)
#define CHUNK    1024
#define NTHREADS 512

// smem floats: Wq 32*512 = 16384, h 128, gact 512, xbuf 2048  (~78 KB)
#define SMEM_FLOATS (KSQ * 4 * G_DIM + H_DIM + G_DIM + CHUNK * 2)

__device__ __forceinline__ unsigned long long pk2(float lo, float hi) {
    unsigned long long r;
    asm("mov.b64 %0, {%1,%2};" : "=l"(r) : "f"(lo), "f"(hi));
    return r;
}
__device__ __forceinline__ float2 upk2(unsigned long long v) {
    float2 r;
    asm("mov.b64 {%0,%1}, %2;" : "=f"(r.x), "=f"(r.y) : "l"(v));
    return r;
}
// d = a*b + c, packed 2x fp32 (SASS FFMA2)
__device__ __forceinline__ unsigned long long ffma2(unsigned long long a,
                                                    unsigned long long b,
                                                    unsigned long long c) {
    unsigned long long d;
    asm("fma.rn.f32x2 %0, %1, %2, %3;" : "=l"(d) : "l"(a), "l"(b), "l"(c));
    return d;
}

__device__ __forceinline__ float sigmoid_f(float x) {
    return __fdividef(1.0f, 1.0f + __expf(-x));
}
__device__ __forceinline__ float tanh_f(float x) {
    return 1.0f - __fdividef(2.0f, 1.0f + __expf(2.0f * x));
}

__global__ void __launch_bounds__(NTHREADS, 1)
lstm_persistent_kernel(const float* __restrict__ sentence,
                       const float* __restrict__ W_ih,
                       const float* __restrict__ W_hh,
                       const float* __restrict__ b_ih,
                       const float* __restrict__ b_hh,
                       const float* __restrict__ W_out,
                       const float* __restrict__ b_out,
                       float* __restrict__ out)
{
    extern __shared__ float smem[];
    // ulonglong2 quad layout: Wq[j*G_DIM + r] covers cols 96+4j .. 96+4j+3 of row r
    ulonglong2* Wq  = (ulonglong2*)smem;                 // KSQ*G_DIM ulonglong2
    float* h_sh = smem + KSQ * 4 * G_DIM;                // 128
    float* gact = h_sh + H_DIM;                          // 512
    float* xbuf = gact + G_DIM;                          // CHUNK*2

    const int r = threadIdx.x;               // gate row 0..511
    const int gate = r >> 7;                 // 0=i 1=f 2=g(tanh) 3=o

    const float wih0 = W_ih[2 * r + 0];
    const float wih1 = W_ih[2 * r + 1];
    const float br   = b_ih[r] + b_hh[r];

    // 96 register-resident weight columns as 48 packed pairs
    unsigned long long Wp[KRP];
#pragma unroll
    for (int p = 0; p < KRP; ++p)
        Wp[p] = pk2(W_hh[r * H_DIM + 2 * p], W_hh[r * H_DIM + 2 * p + 1]);

    // 32 smem-resident columns as 8 quads per row, [quad][row] layout
#pragma unroll
    for (int j = 0; j < KSQ; ++j) {
        const int k0 = 2 * KRP + 4 * j;
        ulonglong2 w;
        w.x = pk2(W_hh[r * H_DIM + k0 + 0], W_hh[r * H_DIM + k0 + 1]);
        w.y = pk2(W_hh[r * H_DIM + k0 + 2], W_hh[r * H_DIM + k0 + 3]);
        Wq[j * G_DIM + r] = w;
    }

    float c_reg = 0.0f;                      // valid for r < 128
    if (r < H_DIM) h_sh[r] = 0.0f;
    __syncthreads();

    for (int t0 = 0; t0 < L_SEQ; t0 += CHUNK) {
        // Refill x chunk: 2048 floats = 512 float4, one per thread.
        ((float4*)xbuf)[r] = ((const float4*)(sentence + 2 * t0))[r];
        __syncthreads();

#pragma unroll 1
        for (int ti = 0; ti < CHUNK; ++ti) {
            const float x0 = xbuf[2 * ti + 0];
            const float x1 = xbuf[2 * ti + 1];
            unsigned long long acc_a = pk2(fmaf(wih0, x0, br), wih1 * x1);
            unsigned long long acc_b = 0ULL; // bit pattern of (0.0f, 0.0f)

            // h as packed pairs; each 128-bit load = 2 aligned u64 pairs
            const ulonglong2* h2 = (const ulonglong2*)h_sh;

            // k in [0,96): weights from registers
#pragma unroll
            for (int q = 0; q < KRP / 2; ++q) {
                const ulonglong2 hp = h2[q];
                acc_a = ffma2(Wp[2 * q + 0], hp.x, acc_a);
                acc_b = ffma2(Wp[2 * q + 1], hp.y, acc_b);
            }
            // k in [96,128): weights from shared
#pragma unroll
            for (int j = 0; j < KSQ; ++j) {
                const ulonglong2 hp = h2[KRP / 2 + j];
                const ulonglong2 wp = Wq[j * G_DIM + r];
                acc_a = ffma2(wp.x, hp.x, acc_a);
                acc_b = ffma2(wp.y, hp.y, acc_b);
            }
            const float2 sa = upk2(acc_a);
            const float2 sb = upk2(acc_b);
            const float g = (sa.x + sa.y) + (sb.x + sb.y);

            // Activation: warp-uniform branch (gate constant per 4 warps)
            gact[r] = (gate == 2) ? tanh_f(g) : sigmoid_f(g);
            __syncthreads();

            if (r < H_DIM) {
                const float iv = gact[r];
                const float fv = gact[H_DIM + r];
                const float gv = gact[2 * H_DIM + r];
                const float ov = gact[3 * H_DIM + r];
                c_reg = fmaf(fv, c_reg, iv * gv);
                h_sh[r] = ov * tanh_f(c_reg);
            }
            __syncthreads();
        }
    }

    // out[0] = sigmoid(h.W_out + b_out); out[1..128] = h_n; out[129..256] = c_n
    if (r < H_DIM) {
        out[1 + r]         = h_sh[r];
        out[1 + H_DIM + r] = c_reg;
    }
    if (r < 32) {
        float s = 0.0f;
#pragma unroll
        for (int m = 0; m < 4; ++m)
            s = fmaf(h_sh[4 * r + m], W_out[4 * r + m], s);
#pragma unroll
        for (int off = 16; off > 0; off >>= 1)
            s += __shfl_xor_sync(0xffffffffu, s, off);
        if (r == 0) out[0] = sigmoid_f(s + b_out[0]);
    }
}

extern "C" void kernel_launch(void* const* d_in, const int* in_sizes, int n_in,
                              void* d_out, int out_size)
{
    const float* sentence = (const float*)d_in[0];
    const float* W_ih     = (const float*)d_in[1];
    const float* W_hh     = (const float*)d_in[2];
    const float* b_ih     = (const float*)d_in[3];
    const float* b_hh     = (const float*)d_in[4];
    const float* W_out    = (const float*)d_in[5];
    const float* b_out    = (const float*)d_in[6];
    float* out            = (float*)d_out;

    const size_t smem_bytes = (size_t)SMEM_FLOATS * sizeof(float);
    cudaFuncSetAttribute(lstm_persistent_kernel,
                         cudaFuncAttributeMaxDynamicSharedMemorySize,
                         (int)smem_bytes);

    lstm_persistent_kernel<<<1, NTHREADS, smem_bytes>>>(
        sentence, W_ih, W_hh, b_ih, b_hh, W_out, b_out, out);
}

// round 6
// speedup vs baseline: 2.7060x; 2.3503x over previous
#include <cuda_runtime.h>
#include <cstdint>

// LSTMTagger: 262144 sequential steps, H=128 (512 gate rows), I=2.
// R5: 4-CTA cluster. CTA c owns h[32c:32c+32), computes its 128 gate rows
// with ALL weights in registers (128 fp32/thread). Per-step h exchange via
// DSMEM stores + mbarrier (release-arrive per producer lane, acquire wait).
// Double-buffered h; one mbarrier phase per step. Full fp32 numerics.

#define L_SEQ     262144
#define H_DIM     128
#define SLICE     32
#define CLUSTER_N 4
#define NTHREADS  128
#define CHUNK     1024

__device__ __forceinline__ float sigmoid_f(float x) {
    return __fdividef(1.0f, 1.0f + __expf(-x));
}
__device__ __forceinline__ float tanh_f(float x) {
    return 1.0f - __fdividef(2.0f, 1.0f + __expf(2.0f * x));
}

__device__ __forceinline__ uint32_t smem_u32(const void* p) {
    uint32_t a;
    asm("{ .reg .u64 t; cvta.to.shared.u64 t, %1; cvt.u32.u64 %0, t; }"
        : "=r"(a) : "l"(p));
    return a;
}
__device__ __forceinline__ uint32_t cluster_rank() {
    uint32_t r; asm("mov.u32 %0, %%cluster_ctarank;" : "=r"(r)); return r;
}
__device__ __forceinline__ uint32_t mapa_u32(uint32_t addr, uint32_t rank) {
    uint32_t r;
    asm("mapa.shared::cluster.u32 %0, %1, %2;" : "=r"(r) : "r"(addr), "r"(rank));
    return r;
}
__device__ __forceinline__ void sts_cluster_f32(uint32_t raddr, float v) {
    asm volatile("st.shared::cluster.f32 [%0], %1;"
                 :: "r"(raddr), "f"(v) : "memory");
}
// release-semantics arrive on a (possibly remote) cluster smem barrier
__device__ __forceinline__ void mbar_arrive_cluster(uint32_t raddr) {
    asm volatile("mbarrier.arrive.shared::cluster.b64 _, [%0];"
                 :: "r"(raddr) : "memory");
}
__device__ __forceinline__ void mbar_init(uint32_t addr, uint32_t count) {
    asm volatile("mbarrier.init.shared.b64 [%0], %1;"
                 :: "r"(addr), "r"(count) : "memory");
}
// acquire at CLUSTER scope so peer DSMEM stores are visible after the wait
__device__ __forceinline__ void mbar_wait_parity_acq_cluster(uint32_t addr,
                                                             uint32_t parity) {
    uint32_t done;
    asm volatile(
        "{\n\t.reg .pred p;\n\t"
        "mbarrier.try_wait.parity.acquire.cluster.shared::cta.b64 p, [%1], %2;\n\t"
        "selp.b32 %0, 1, 0, p;\n\t}"
        : "=r"(done) : "r"(addr), "r"(parity) : "memory");
    if (!done) {
        asm volatile(
            "{\n\t.reg .pred P1;\n\t"
            "WL_%=:\n\t"
            "mbarrier.try_wait.parity.acquire.cluster.shared::cta.b64 P1, [%0], %1, 0x989680;\n\t"
            "@P1 bra.uni WD_%=;\n\t"
            "bra.uni WL_%=;\n\t"
            "WD_%=:\n\t}"
            :: "r"(addr), "r"(parity) : "memory");
    }
}
#define CLUSTER_SYNC_() do { \
    asm volatile("barrier.cluster.arrive.aligned;" ::: "memory"); \
    asm volatile("barrier.cluster.wait.aligned;" ::: "memory"); \
} while (0)

__global__ void __launch_bounds__(NTHREADS, 1) __cluster_dims__(CLUSTER_N, 1, 1)
lstm_cluster_kernel(const float* __restrict__ sentence,
                    const float* __restrict__ W_ih,
                    const float* __restrict__ W_hh,
                    const float* __restrict__ b_ih,
                    const float* __restrict__ b_hh,
                    const float* __restrict__ W_out,
                    const float* __restrict__ b_out,
                    float* __restrict__ out)
{
    __shared__ alignas(8)  unsigned long long mbar;
    __shared__ alignas(16) float hbuf[2][H_DIM];
    __shared__ alignas(16) float gact[NTHREADS];
    __shared__ alignas(16) float xbuf[CHUNK * 2];

    const int r    = threadIdx.x;     // 0..127
    const int lane = r & 31;
    const int gate = r >> 5;          // 0=i 1=f 2=g(tanh) 3=o (warp-uniform)
    const uint32_t rank = cluster_rank();

    // global gate row this thread owns
    const int gr = gate * H_DIM + (int)rank * SLICE + lane;

    const float wih0 = W_ih[2 * gr + 0];
    const float wih1 = W_ih[2 * gr + 1];
    const float br   = b_ih[gr] + b_hh[gr];

    // Entire W_hh row in registers (128 fp32)
    float W[H_DIM];
#pragma unroll
    for (int k = 0; k < H_DIM; ++k) W[k] = W_hh[gr * H_DIM + k];

    // init smem / barrier
    hbuf[0][r] = 0.0f;
    hbuf[1][r] = 0.0f;
    const uint32_t bar_addr = smem_u32(&mbar);
    const uint32_t hb_addr  = smem_u32(&hbuf[0][0]);
    if (r == 0) mbar_init(bar_addr, SLICE * CLUSTER_N);   // 128 arrivals/phase
    __syncthreads();
    CLUSTER_SYNC_();   // barriers + zeroed h visible cluster-wide

    // producer-side peer addresses (self included, uniform code)
    uint32_t peer_h[CLUSTER_N], peer_bar[CLUSTER_N];
#pragma unroll
    for (int p = 0; p < CLUSTER_N; ++p) {
        peer_h[p]   = mapa_u32(hb_addr, p);
        peer_bar[p] = mapa_u32(bar_addr, p);
    }
    const uint32_t slice_byte = ((uint32_t)rank * SLICE + lane) * 4u;

    float c_reg = 0.0f;   // valid for gate==0 lanes: c[32*rank + lane]

    for (int t0 = 0; t0 < L_SEQ; t0 += CHUNK) {
        // refill x chunk: 2048 floats, 128 threads x 4 float4
        {
            const float4* src = (const float4*)(sentence + 2 * t0);
            float4* dst = (float4*)xbuf;
#pragma unroll
            for (int j = 0; j < 4; ++j) dst[r + j * NTHREADS] = src[r + j * NTHREADS];
        }
        __syncthreads();

#pragma unroll 1
        for (int ti = 0; ti < CHUNK; ++ti) {
            const int t = t0 + ti;
            const float4* h4 = (const float4*)hbuf[t & 1];
            const float x0 = xbuf[2 * ti + 0];
            const float x1 = xbuf[2 * ti + 1];

            float acc0 = fmaf(wih0, x0, br);
            float acc1 = wih1 * x1;
            float acc2 = 0.0f, acc3 = 0.0f;
#pragma unroll
            for (int q = 0; q < H_DIM / 4; ++q) {
                const float4 hv = h4[q];
                acc0 = fmaf(W[4 * q + 0], hv.x, acc0);
                acc1 = fmaf(W[4 * q + 1], hv.y, acc1);
                acc2 = fmaf(W[4 * q + 2], hv.z, acc2);
                acc3 = fmaf(W[4 * q + 3], hv.w, acc3);
            }
            const float g = (acc0 + acc2) + (acc1 + acc3);

            gact[r] = (gate == 2) ? tanh_f(g) : sigmoid_f(g);
            __syncthreads();

            if (gate == 0) {   // warp 0: producers for this CTA's h slice
                const float iv = gact[lane];
                const float fv = gact[32 + lane];
                const float gv = gact[64 + lane];
                const float ov = gact[96 + lane];
                c_reg = fmaf(fv, c_reg, iv * gv);
                const float h = ov * tanh_f(c_reg);

                const uint32_t off = (uint32_t)(((t + 1) & 1) * H_DIM) * 4u + slice_byte;
#pragma unroll
                for (int p = 0; p < CLUSTER_N; ++p)
                    sts_cluster_f32(peer_h[p] + off, h);
#pragma unroll
                for (int p = 0; p < CLUSTER_N; ++p)
                    mbar_arrive_cluster(peer_bar[p]);
            }
            // all threads: wait for full h(t+1) (acquire, cluster scope)
            mbar_wait_parity_acq_cluster(bar_addr, (uint32_t)(t & 1));
        }
    }

    // Outputs (L even -> final h in hbuf[0]):
    // out[0]=sigmoid(h.W_out+b), out[1..128]=h_n, out[129..256]=c_n
    if (gate == 0)
        out[1 + H_DIM + (int)rank * SLICE + lane] = c_reg;
    if (rank == 0) {
        out[1 + r] = hbuf[0][r];
        if (r < 32) {
            float s = 0.0f;
#pragma unroll
            for (int m = 0; m < 4; ++m)
                s = fmaf(hbuf[0][4 * r + m], W_out[4 * r + m], s);
#pragma unroll
            for (int off = 16; off > 0; off >>= 1)
                s += __shfl_xor_sync(0xffffffffu, s, off);
            if (r == 0) out[0] = sigmoid_f(s + b_out[0]);
        }
    }
    CLUSTER_SYNC_();
}

extern "C" void kernel_launch(void* const* d_in, const int* in_sizes, int n_in,
                              void* d_out, int out_size)
{
    const float* sentence = (const float*)d_in[0];
    const float* W_ih     = (const float*)d_in[1];
    const float* W_hh     = (const float*)d_in[2];
    const float* b_ih     = (const float*)d_in[3];
    const float* b_hh     = (const float*)d_in[4];
    const float* W_out    = (const float*)d_in[5];
    const float* b_out    = (const float*)d_in[6];
    float* out            = (float*)d_out;

    lstm_cluster_kernel<<<CLUSTER_N, NTHREADS>>>(
        sentence, W_ih, W_hh, b_ih, b_hh, W_out, b_out, out);
}